// round 12
// baseline (speedup 1.0000x reference)
#include <cuda_runtime.h>
#include <cuda_bf16.h>
#include <math.h>

// Problem dims
#define NT_ 730
#define NS_ 2000
#define NH_ 16
#define NG_ 32
#define NR_ 15

#define NTPAD_ 744          // g_v4 / g_pe planes (prefetch overrun pad)
#define NTQ_   736          // g_Qs planes (scan writes t<736)

// ---------------- scratch (device globals; no allocations allowed) ----------------
__device__ float g_hfc [NS_ * 256];
__device__ float g_hR  [NS_ * 256];
__device__ float g_base1[NS_ * 256];
__device__ float g_base2[NS_ * 256];
__device__ float g_params[8][NS_ * NH_];
__device__ float g_rr  [NS_ * NH_ * 16];          // ga*relu(wR) taps, lag-indexed
__device__ uint2  g_PWb [2048];                   // G1 weights, bf16x2 frag-packed
__device__ uint2  g_PWt [2048];                   // G2 weights, tf32 frag-packed
__device__ float  g_c1  [256];                    // fcT1_W1 LAI col
__device__ float4 g_dvec[256];                    // fcT2_W1 {R,T1,T2} cols
__device__ float  g_bias48[48];
__device__ float4 g_v4 [NTPAD_ * NS_ * NH_];      // {Pl1, Pl2, vk, vm}
__device__ float2 g_pe [NTPAD_ * NS_];            // {Ps, E}
__device__ float  g_Qs [NTQ_ * NS_ * NH_];        // per-lane Q1+Q2+Q3

// ---------------- helpers ----------------
__device__ __forceinline__ float tanh_hw(float x) {
    float y;
    asm("tanh.approx.f32 %0, %1;" : "=f"(y) : "f"(x));
    return y;
}
__device__ __forceinline__ unsigned cvt_tf32(float f) {
    unsigned u;
    asm("cvt.rna.tf32.f32 %0, %1;" : "=r"(u) : "f"(f));
    return u;
}
// pack two floats to bf16x2: lo -> low half, hi -> high half
__device__ __forceinline__ unsigned pack_bf16(float lo, float hi) {
    unsigned r;
    asm("cvt.rn.bf16x2.f32 %0, %1, %2;" : "=r"(r) : "f"(hi), "f"(lo));
    return r;
}
#define MMA_TF32(D, a0, a1, a2, a3, b0, b1)                                   \
    asm("mma.sync.aligned.m16n8k8.row.col.f32.tf32.tf32.f32 "                 \
        "{%0,%1,%2,%3}, {%4,%5,%6,%7}, {%8,%9}, {%0,%1,%2,%3};"               \
        : "+f"((D)[0]), "+f"((D)[1]), "+f"((D)[2]), "+f"((D)[3])              \
        : "r"(a0), "r"(a1), "r"(a2), "r"(a3), "r"(b0), "r"(b1))
#define MMA_BF16(D, a0, a1, a2, a3, b0, b1)                                   \
    asm("mma.sync.aligned.m16n8k16.row.col.f32.bf16.bf16.f32 "                \
        "{%0,%1,%2,%3}, {%4,%5,%6,%7}, {%8,%9}, {%0,%1,%2,%3};"               \
        : "+f"((D)[0]), "+f"((D)[1]), "+f"((D)[2]), "+f"((D)[3])              \
        : "r"(a0), "r"(a1), "r"(a2), "r"(a3), "r"(b0), "r"(b1))

// ============================================================================
// Kernel 1a: per-basin hidden activations + time-invariant layer-1 bases
// ============================================================================
__global__ void __launch_bounds__(256) k_hidden(
    const float* __restrict__ xc,
    const float* __restrict__ fc_W1,  const float* __restrict__ fc_b1,
    const float* __restrict__ fcR_W1, const float* __restrict__ fcR_b1,
    const float* __restrict__ fcT1_W1, const float* __restrict__ fcT1_b1,
    const float* __restrict__ fcT2_W1, const float* __restrict__ fcT2_b1)
{
    __shared__ float xcs[8][NG_];
    const int tid = threadIdx.x;
    const int s0  = blockIdx.x * 8;
    xcs[tid >> 5][tid & 31] = xc[s0 * NG_ + tid];
    __syncthreads();

    const int j = tid;
    float acc[8];

    {
        float b = fc_b1[j];
#pragma unroll
        for (int i = 0; i < 8; i++) acc[i] = b;
        const float4* row = (const float4*)(fc_W1 + j * NG_);
#pragma unroll
        for (int q = 0; q < 8; q++) {
            float4 w = row[q];
#pragma unroll
            for (int i = 0; i < 8; i++) {
                acc[i] = fmaf(w.x, xcs[i][4*q+0], acc[i]);
                acc[i] = fmaf(w.y, xcs[i][4*q+1], acc[i]);
                acc[i] = fmaf(w.z, xcs[i][4*q+2], acc[i]);
                acc[i] = fmaf(w.w, xcs[i][4*q+3], acc[i]);
            }
        }
#pragma unroll
        for (int i = 0; i < 8; i++) g_hfc[(s0 + i) * 256 + j] = tanhf(acc[i]);
    }
    {
        float b = fcR_b1[j];
#pragma unroll
        for (int i = 0; i < 8; i++) acc[i] = b;
        const float4* row = (const float4*)(fcR_W1 + j * NG_);
#pragma unroll
        for (int q = 0; q < 8; q++) {
            float4 w = row[q];
#pragma unroll
            for (int i = 0; i < 8; i++) {
                acc[i] = fmaf(w.x, xcs[i][4*q+0], acc[i]);
                acc[i] = fmaf(w.y, xcs[i][4*q+1], acc[i]);
                acc[i] = fmaf(w.z, xcs[i][4*q+2], acc[i]);
                acc[i] = fmaf(w.w, xcs[i][4*q+3], acc[i]);
            }
        }
#pragma unroll
        for (int i = 0; i < 8; i++) g_hR[(s0 + i) * 256 + j] = tanhf(acc[i]);
    }
    {
        float b = fcT1_b1[j];
#pragma unroll
        for (int i = 0; i < 8; i++) acc[i] = b;
        const float* row = fcT1_W1 + j * 33 + 1;
#pragma unroll
        for (int g = 0; g < NG_; g++) {
            float w = row[g];
#pragma unroll
            for (int i = 0; i < 8; i++) acc[i] = fmaf(w, xcs[i][g], acc[i]);
        }
#pragma unroll
        for (int i = 0; i < 8; i++) g_base1[(s0 + i) * 256 + j] = acc[i];
    }
    {
        float b = fcT2_b1[j];
#pragma unroll
        for (int i = 0; i < 8; i++) acc[i] = b;
        const float* row = fcT2_W1 + j * 35 + 3;
#pragma unroll
        for (int g = 0; g < NG_; g++) {
            float w = row[g];
#pragma unroll
            for (int i = 0; i < 8; i++) acc[i] = fmaf(w, xcs[i][g], acc[i]);
        }
#pragma unroll
        for (int i = 0; i < 8; i++) g_base2[(s0 + i) * 256 + j] = acc[i];
    }
}

// ============================================================================
// Kernel 1b: per-basin output layers -> scan params + routing taps
// ============================================================================
__global__ void __launch_bounds__(256) k_outputs(
    const float* __restrict__ fc_W2,  const float* __restrict__ fc_b2,
    const float* __restrict__ fcR_W2, const float* __restrict__ fcR_b2)
{
    __shared__ float hf[8][256];
    __shared__ float hr[8][256];
    __shared__ float w8[8][160];
    __shared__ float r8[8][240];
    __shared__ float ga8[8][NH_];

    const int tid = threadIdx.x;
    const int s0  = blockIdx.x * 8;

    for (int idx = tid; idx < 2048; idx += 256) {
        int b = idx >> 8, j = idx & 255;
        hf[b][j] = g_hfc[(s0 + b) * 256 + j];
        hr[b][j] = g_hR [(s0 + b) * 256 + j];
    }
    __syncthreads();

    if (tid < 160) {
        const int o = tid;
        float acc[8];
        float bb = fc_b2[o];
#pragma unroll
        for (int i = 0; i < 8; i++) acc[i] = bb;
        const float4* row = (const float4*)(fc_W2 + o * 256);
        for (int q = 0; q < 64; q++) {
            float4 w = row[q];
#pragma unroll
            for (int i = 0; i < 8; i++) {
                acc[i] = fmaf(w.x, hf[i][4*q+0], acc[i]);
                acc[i] = fmaf(w.y, hf[i][4*q+1], acc[i]);
                acc[i] = fmaf(w.z, hf[i][4*q+2], acc[i]);
                acc[i] = fmaf(w.w, hf[i][4*q+3], acc[i]);
            }
        }
#pragma unroll
        for (int i = 0; i < 8; i++) w8[i][o] = acc[i];
    }
    if (tid < 240) {
        const int o = tid;
        float acc[8];
        float bb = fcR_b2[o];
#pragma unroll
        for (int i = 0; i < 8; i++) acc[i] = bb;
        const float4* row = (const float4*)(fcR_W2 + o * 256);
        for (int q = 0; q < 64; q++) {
            float4 w = row[q];
#pragma unroll
            for (int i = 0; i < 8; i++) {
                acc[i] = fmaf(w.x, hr[i][4*q+0], acc[i]);
                acc[i] = fmaf(w.y, hr[i][4*q+1], acc[i]);
                acc[i] = fmaf(w.z, hr[i][4*q+2], acc[i]);
                acc[i] = fmaf(w.w, hr[i][4*q+3], acc[i]);
            }
        }
#pragma unroll
        for (int i = 0; i < 8; i++) r8[i][o] = fmaxf(acc[i], 0.f);
    }
    __syncthreads();

    if (tid < 128) {
        const int b = tid >> 4, h = tid & 15;
        const float* wb = w8[b];
        float k1  = 1.f / (1.f + expf(-wb[16  + h]));
        float k2  = 1.f / (1.f + expf(-wb[32  + h]));
        float k23 = 1.f / (1.f + expf(-wb[48  + h]));
        float k3  = (1.f / (1.f + expf(-wb[64 + h]))) * 0.1f;
        float gl  = expf(wb[80 + h]) * 2.f;
        float qb  = fmaxf(wb[112 + h], 0.f);
        float ge1 = fmaxf(wb[128 + h], 0.f);
        float ge2 = fmaxf(wb[144 + h], 0.f);
        float m = wb[96];
        for (int i = 1; i < 16; i++) m = fmaxf(m, wb[96 + i]);
        float sum = 0.f;
        for (int i = 0; i < 16; i++) sum += expf(wb[96 + i] - m);
        float ga = expf(wb[96 + h] - m) / sum;
        ga8[b][h] = ga;

        const int lane = (s0 + b) * NH_ + h;
        g_params[0][lane] = k1;
        g_params[1][lane] = k2;
        g_params[2][lane] = k23;
        g_params[3][lane] = k3;
        g_params[4][lane] = gl;
        g_params[5][lane] = qb;
        g_params[6][lane] = ge1;
        g_params[7][lane] = ge2;
        g_rr[lane * 16 + 15] = 0.f;
    }
    __syncthreads();

    for (int idx = tid; idx < 8 * 240; idx += 256) {
        int b = idx / 240, o = idx % 240;
        int h = o / NR_, jj = o % NR_;
        int lane = (s0 + b) * NH_ + h;
        g_rr[lane * 16 + (14 - jj)] = ga8[b][h] * r8[b][o];
    }
}

// ============================================================================
// Kernel 1c: pack layer-2 weights into mma fragment layouts.
//   G1 (fcT1_W2, 32 outs) -> bf16x2 m16n8k16 B-frags: [kc][nt 0..3][lane]
//   G2 (fcT2_W2, 16 outs) -> tf32  m16n8k8  B-frags: [kk][nt 0..1][lane]
// grid 18 x 256 = 4608 threads
// ============================================================================
__global__ void __launch_bounds__(256) k_prep(
    const float* __restrict__ fcT1_W1, const float* __restrict__ fcT1_W2,
    const float* __restrict__ fcT1_b2,
    const float* __restrict__ fcT2_W1, const float* __restrict__ fcT2_W2,
    const float* __restrict__ fcT2_b2)
{
    const int idx = blockIdx.x * 256 + threadIdx.x;
    if (idx < 2048) {
        // G1 bf16: kc = idx/128, rem: nt = rem/32, lane = rem%32
        const int kc   = idx >> 7;
        const int rem  = idx & 127;
        const int nt   = rem >> 5;
        const int lane = rem & 31;
        const int rq = lane >> 2, qk = lane & 3;
        const int o  = nt * 8 + rq;
        const int k0 = kc * 16;
        uint2 u;
        u.x = pack_bf16(fcT1_W2[o * 256 + k0 + 2 * qk],
                        fcT1_W2[o * 256 + k0 + 2 * qk + 1]);
        u.y = pack_bf16(fcT1_W2[o * 256 + k0 + 8 + 2 * qk],
                        fcT1_W2[o * 256 + k0 + 8 + 2 * qk + 1]);
        g_PWb[idx] = u;
    } else if (idx < 4096) {
        // G2 tf32: i2 = idx-2048; kk = i2/64, nt = (i2%64)/32, lane = i2%32
        const int i2   = idx - 2048;
        const int kk   = i2 >> 6;
        const int rem  = i2 & 63;
        const int nt   = rem >> 5;
        const int lane = rem & 31;
        const int rq = lane >> 2, qk = lane & 3;
        const int o = nt * 8 + rq;
        const int j = kk * 8 + qk;
        uint2 u;
        u.x = cvt_tf32(fcT2_W2[o * 256 + j]);
        u.y = cvt_tf32(fcT2_W2[o * 256 + j + 4]);
        g_PWt[i2] = u;
    } else if (idx < 4352) {
        const int j = idx - 4096;
        g_c1[j] = fcT1_W1[j * 33];
        float4 dv;
        dv.x = fcT2_W1[j * 35 + 0];
        dv.y = fcT2_W1[j * 35 + 1];
        dv.z = fcT2_W1[j * 35 + 2];
        dv.w = 0.f;
        g_dvec[j] = dv;
    } else if (idx < 4400) {
        const int b = idx - 4352;
        g_bias48[b] = (b < 32) ? fcT1_b2[b] : fcT2_b2[b - 32];
    }
}

// ============================================================================
// Kernel 2: tensor-core per-(t,s) MLPs -> {Pl1,Pl2,vk,vm} + {Ps,E}
// block = 2 basins x 128 timesteps, 8 warps; G1 bf16 k16, G2 tf32 k8
// ============================================================================
// smem word offsets
#define SMO_DVEC  0                       // float4[256]   -> 1024 words
#define SMO_PWB   1024                    // uint2[2048]   -> 4096
#define SMO_PWT   5120                    // uint2[2048]   -> 4096
#define SMO_COEF1 9216                    // float2[512]   -> 1024
#define SMO_BASE2 10240                   // float [512]   -> 512
#define SMO_XS    10752                   // float4[256]   -> 1024 {Ta,Tb,Rv,LAI}
#define SMO_PL    11776                   // float [256]   -> 256
#define SMO_BIAS  12032                   // float [48]
#define KM_SMEM_WORDS 12080
#define KM_SMEM_BYTES (KM_SMEM_WORDS * 4)

__global__ void __launch_bounds__(256) k_mlp_tc(const float* __restrict__ x)
{
    extern __shared__ float sm[];
    float4* sdvec  = (float4*)(sm + SMO_DVEC);
    uint2*  sPWb   = (uint2*)(sm + SMO_PWB);
    uint2*  sPWt   = (uint2*)(sm + SMO_PWT);
    float2* scoef1 = (float2*)(sm + SMO_COEF1);
    float*  sbase2 = sm + SMO_BASE2;
    float4* sxs    = (float4*)(sm + SMO_XS);
    float*  sPL    = sm + SMO_PL;
    float*  sbias  = sm + SMO_BIAS;

    const int tid = threadIdx.x;
    const int s0  = blockIdx.x * 2;
    const int t0  = blockIdx.y << 7;

    for (int i = tid; i < 2048; i += 256) {
        sPWb[i] = g_PWb[i];
        sPWt[i] = g_PWt[i];
    }
    for (int i = tid; i < 256; i += 256) sdvec[i] = g_dvec[i];
    for (int i = tid; i < 512; i += 256) {
        int g = i >> 8, j = i & 255;
        scoef1[i] = make_float2(g_base1[(s0 + g) * 256 + j], g_c1[j]);
        sbase2[i] = g_base2[(s0 + g) * 256 + j];
    }
    if (tid < 48) sbias[tid] = g_bias48[tid];

    // prologue: forcings + vp/Ps/Pl per (basin, row)
    {
        const int g = tid >> 7, r = tid & 127;
        const int t = t0 + r;
        const int s = s0 + g;
        float P = 0.f, E = 0.f, Ta = 0.f, Tb = 0.f, Rv = 0.f, LAI = 0.f;
        if (t < NT_) {
            const float* xr = x + ((size_t)t * NS_ + s) * 6;
            P = __ldg(xr); E = __ldg(xr + 1); Ta = __ldg(xr + 2);
            Tb = __ldg(xr + 3); Rv = __ldg(xr + 4); LAI = __ldg(xr + 5);
        }
        sxs[g * 128 + r] = make_float4(Ta, Tb, Rv, LAI);

        float den = Tb - Ta;
        float ra  = (Ta + Tb) / (den == 0.f ? 1.f : den);
        ra = fminf(fmaxf(ra, -1.f), 1.f);
        if (Ta >= 0.f || Tb <= 0.f) ra = 0.f;
        float vp = 1.f - acosf(ra) * (1.f / 3.1415f);
        if (Ta >= 0.f) vp = 1.f;
        if (Tb <= 0.f) vp = 0.f;
        float Ps = P * (1.f - vp);
        float Pl = P * vp;
        sPL[g * 128 + r] = Pl;
        if (t < NT_) __stcs(g_pe + (size_t)t * NS_ + s, make_float2(Ps, E));
    }
    __syncthreads();

    const int g    = tid >> 7;
    const int wl   = (tid >> 5) & 3;
    const int lane = tid & 31;
    const int rq = lane >> 2, qk = lane & 3;
    const int rbase = wl * 32 + rq;
    const int s = s0 + g;

    float LAI[4], Rv[4], Ta[4], Tb[4];
#pragma unroll
    for (int i = 0; i < 4; i++) {
        float4 xr = sxs[g * 128 + rbase + i * 8];
        Ta[i] = xr.x; Tb[i] = xr.y; Rv[i] = xr.z; LAI[i] = xr.w;
    }

    float dacc[2][6][4];
#pragma unroll
    for (int mt = 0; mt < 2; mt++)
#pragma unroll
        for (int nt = 0; nt < 6; nt++)
#pragma unroll
            for (int r = 0; r < 4; r++) dacc[mt][nt][r] = 0.f;

#pragma unroll 2
    for (int kc = 0; kc < 16; kc++) {
        // ---- G1: bf16 m16n8k16, h1 = tanh(base1 + LAI*c1), n-tiles 0..3 ----
        {
            const int j0 = kc * 16 + 2 * qk;
            // float4 = {base1[j0], c1[j0], base1[j0+1], c1[j0+1]}
            float4 cLo = *(const float4*)(scoef1 + g * 256 + j0);
            float4 cHi = *(const float4*)(scoef1 + g * 256 + j0 + 8);
            const uint2* pbB = sPWb + kc * 128 + lane;
#pragma unroll
            for (int mt = 0; mt < 2; mt++) {
                const float Llo = LAI[2 * mt], Lhi = LAI[2 * mt + 1];
                unsigned a0 = pack_bf16(tanh_hw(fmaf(Llo, cLo.y, cLo.x)),
                                        tanh_hw(fmaf(Llo, cLo.w, cLo.z)));
                unsigned a1 = pack_bf16(tanh_hw(fmaf(Lhi, cLo.y, cLo.x)),
                                        tanh_hw(fmaf(Lhi, cLo.w, cLo.z)));
                unsigned a2 = pack_bf16(tanh_hw(fmaf(Llo, cHi.y, cHi.x)),
                                        tanh_hw(fmaf(Llo, cHi.w, cHi.z)));
                unsigned a3 = pack_bf16(tanh_hw(fmaf(Lhi, cHi.y, cHi.x)),
                                        tanh_hw(fmaf(Lhi, cHi.w, cHi.z)));
#pragma unroll
                for (int nt = 0; nt < 4; nt++) {
                    uint2 b = pbB[nt * 32];
                    MMA_BF16(dacc[mt][nt], a0, a1, a2, a3, b.x, b.y);
                }
            }
        }
        // ---- G2: tf32 m16n8k8 x2, h2 = tanh(base2 + R,T1,T2 dot), n-tiles 4..5 ----
#pragma unroll
        for (int kk = 2 * kc; kk < 2 * kc + 2; kk++) {
            const int j0 = kk * 8 + qk;
            float  b20 = sbase2[g * 256 + j0], b21 = sbase2[g * 256 + j0 + 4];
            float4 dv0 = sdvec[j0],  dv1 = sdvec[j0 + 4];
            const uint2* pbT = sPWt + kk * 64 + lane;
            unsigned aB[8];
#pragma unroll
            for (int i = 0; i < 4; i++) {
                float p = fmaf(Rv[i], dv0.x, b20);
                p = fmaf(Ta[i], dv0.y, p);
                p = fmaf(Tb[i], dv0.z, p);
                float q = fmaf(Rv[i], dv1.x, b21);
                q = fmaf(Ta[i], dv1.y, q);
                q = fmaf(Tb[i], dv1.z, q);
                aB[(i >> 1) * 4 + (i & 1)]     = __float_as_uint(tanh_hw(p));
                aB[(i >> 1) * 4 + 2 + (i & 1)] = __float_as_uint(tanh_hw(q));
            }
#pragma unroll
            for (int nt = 0; nt < 2; nt++) {
                uint2 b = pbT[nt * 32];
                MMA_TF32(dacc[0][4 + nt], aB[0], aB[1], aB[2], aB[3], b.x, b.y);
                MMA_TF32(dacc[1][4 + nt], aB[4], aB[5], aB[6], aB[7], b.x, b.y);
            }
        }
    }

    // register epilogue: thread owns rows {wl*32+mt*16+rq, +8}, h = {hi*8+2qk, +1}
    const float inv6 = 1.f / 6.f;
#pragma unroll
    for (int mt = 0; mt < 2; mt++) {
#pragma unroll
        for (int half = 0; half < 2; half++) {
            const int r = wl * 32 + mt * 16 + rq + half * 8;
            const int t = t0 + r;
            if (t < NT_) {
                const float Pl = sPL[g * 128 + r];
                float4* dst = g_v4 + ((size_t)t * NS_ + s) * NH_;
#pragma unroll
                for (int hi = 0; hi < 2; hi++) {
#pragma unroll
                    for (int c = 0; c < 2; c++) {
                        const int h  = hi * 8 + 2 * qk + c;
                        const int di = half * 2 + c;
                        float vi = __saturatef(fmaf(dacc[mt][hi][di]     + sbias[h],      inv6, 0.5f));
                        float vk = __saturatef(fmaf(dacc[mt][2 + hi][di] + sbias[16 + h], inv6, 0.5f));
                        float vm = __expf(2.f * (dacc[mt][4 + hi][di] + sbias[32 + h]));
                        float Pl2 = Pl * vi;
                        __stcs(dst + h, make_float4(Pl - Pl2, Pl2, vk, vm));
                    }
                }
            }
        }
    }
}

// ============================================================================
// Kernel 3: pure recurrence; 1 lane/thread, 8-deep double-buffered prefetch.
// 92 chunks of 8 t-steps (processes t<736; padding zero-filled and unread).
// ============================================================================
#define PLV_ (NS_ * NH_)

__global__ void __launch_bounds__(128) k_scan3()
{
    const int lane = blockIdx.x * 128 + threadIdx.x;   // 0..31999

    const float k1  = g_params[0][lane];
    const float k2  = g_params[1][lane];
    const float k23 = g_params[2][lane];
    const float k3  = g_params[3][lane];
    const float gl  = g_params[4][lane];
    const float qb  = g_params[5][lane];
    const float ge1 = g_params[6][lane];
    const float ge2 = g_params[7][lane];
    const float c23 = 1.f - k23;

    const float4* pv = g_v4 + lane;
    const float2* pp = g_pe + (lane >> 4);

    float4 bv0[8], bv1[8];
    float2 bp0[8], bp1[8];
#pragma unroll
    for (int u = 0; u < 8; u++) {
        bv0[u] = __ldcs(pv + (size_t)u * PLV_);
        bp0[u] = __ldcs(pp + u * NS_);
    }

    float S0 = 0.f, Sv = 0.f, S2 = 0.f, S3 = 0.f;

#define STEP(V, PE, T)                                                         \
    {                                                                          \
        float H0  = S0 + (PE).x;                                               \
        float qSm = fminf(H0, (V).w);                                          \
        float Hv  = fmaxf(Sv + (V).x - (PE).y * ge1, 0.f);                     \
        float qv  = Sv * (V).z;                                                \
        float H2  = fmaxf(S2 + qSm + qv - (PE).y * ge2 + (V).y, 0.f);          \
        float x1  = H2 - gl;                                                   \
        float Q1  = (x1 > 0.f) ? __powf(x1, k1) : 0.f;                         \
        float q2v = fminf(H2, gl) * k2;                                        \
        float H3  = fmaf(q2v, k23, S3);                                        \
        float Q3  = fmaf(H3, k3, qb);                                          \
        S0 = H0 - qSm;                                                         \
        Sv = Hv - qv;                                                          \
        S2 = H2 - Q1 - q2v;                                                    \
        S3 = H3 - Q3;                                                          \
        __stcs(g_Qs + (size_t)(T) * PLV_ + lane, Q1 + q2v * c23 + Q3);         \
    }

#pragma unroll 1
    for (int c = 0; c < 92; c += 2) {
#pragma unroll
        for (int u = 0; u < 8; u++) {
            bv1[u] = __ldcs(pv + (size_t)((c + 1) * 8 + u) * PLV_);
            bp1[u] = __ldcs(pp + ((c + 1) * 8 + u) * NS_);
        }
#pragma unroll
        for (int u = 0; u < 8; u++) STEP(bv0[u], bp0[u], c * 8 + u)
#pragma unroll
        for (int u = 0; u < 8; u++) {
            bv0[u] = __ldcs(pv + (size_t)((c + 2) * 8 + u) * PLV_);
            bp0[u] = __ldcs(pp + ((c + 2) * 8 + u) * NS_);
        }
#pragma unroll
        for (int u = 0; u < 8; u++) STEP(bv1[u], bp1[u], (c + 1) * 8 + u)
    }
#undef STEP
}

// ============================================================================
// Kernel 4: causal 15-tap routing conv + h-reduction (parallel).
// ============================================================================
__global__ void __launch_bounds__(256) k_route(float* __restrict__ out)
{
    __shared__ float sQ[270 * 20];
    __shared__ float srr[15 * 16];

    const int tid = threadIdx.x;
    const int s   = blockIdx.x;
    const int t0  = blockIdx.y << 8;

    for (int i = tid; i < 270 * 16; i += 256) {
        int row = i >> 4, h = i & 15;
        int tg = t0 + row - 14;
        sQ[row * 20 + h] = (tg >= 0 && tg < NT_)
                         ? g_Qs[(size_t)tg * (NS_ * NH_) + s * NH_ + h] : 0.f;
    }
    if (tid < 240) {
        int d = tid >> 4, h = tid & 15;
        srr[d * 16 + h] = g_rr[(s * NH_ + h) * 16 + d];
    }
    __syncthreads();

    const int t = t0 + tid;
    if (t < NT_) {
        float4 acc = make_float4(0.f, 0.f, 0.f, 0.f);
#pragma unroll
        for (int d = 0; d < 15; d++) {
            const float4* qr  = (const float4*)(sQ + (tid + 14 - d) * 20);
            const float4* rr4 = (const float4*)(srr + d * 16);
#pragma unroll
            for (int hq = 0; hq < 4; hq++) {
                float4 q = qr[hq];
                float4 r = rr4[hq];
                acc.x = fmaf(q.x, r.x, acc.x);
                acc.y = fmaf(q.y, r.y, acc.y);
                acc.z = fmaf(q.z, r.z, acc.z);
                acc.w = fmaf(q.w, r.w, acc.w);
            }
        }
        out[(size_t)t * NS_ + s] = (acc.x + acc.y) + (acc.z + acc.w);
    }
}

// ============================================================================
// launch
// ============================================================================
extern "C" void kernel_launch(void* const* d_in, const int* in_sizes, int n_in,
                              void* d_out, int out_size)
{
    const float* x       = (const float*)d_in[0];
    const float* xc      = (const float*)d_in[1];
    const float* fc_W1   = (const float*)d_in[2];
    const float* fc_b1   = (const float*)d_in[3];
    const float* fc_W2   = (const float*)d_in[4];
    const float* fc_b2   = (const float*)d_in[5];
    const float* fcR_W1  = (const float*)d_in[6];
    const float* fcR_b1  = (const float*)d_in[7];
    const float* fcR_W2  = (const float*)d_in[8];
    const float* fcR_b2  = (const float*)d_in[9];
    const float* fcT1_W1 = (const float*)d_in[10];
    const float* fcT1_b1 = (const float*)d_in[11];
    const float* fcT1_W2 = (const float*)d_in[12];
    const float* fcT1_b2 = (const float*)d_in[13];
    const float* fcT2_W1 = (const float*)d_in[14];
    const float* fcT2_b1 = (const float*)d_in[15];
    const float* fcT2_W2 = (const float*)d_in[16];
    const float* fcT2_b2 = (const float*)d_in[17];
    float* out = (float*)d_out;

    cudaFuncSetAttribute(k_mlp_tc, cudaFuncAttributeMaxDynamicSharedMemorySize, KM_SMEM_BYTES);

    k_hidden<<<NS_ / 8, 256>>>(xc, fc_W1, fc_b1, fcR_W1, fcR_b1,
                               fcT1_W1, fcT1_b1, fcT2_W1, fcT2_b1);
    k_outputs<<<NS_ / 8, 256>>>(fc_W2, fc_b2, fcR_W2, fcR_b2);
    k_prep<<<18, 256>>>(fcT1_W1, fcT1_W2, fcT1_b2, fcT2_W1, fcT2_W2, fcT2_b2);
    k_mlp_tc<<<dim3(NS_ / 2, 6), 256, KM_SMEM_BYTES>>>(x);
    k_scan3<<<(NS_ * NH_) / 128, 128>>>();
    k_route<<<dim3(NS_, 3), 256>>>(out);
}

// round 14
// speedup vs baseline: 1.4161x; 1.4161x over previous
#include <cuda_runtime.h>
#include <cuda_bf16.h>
#include <math.h>

// Problem dims
#define NT_ 730
#define NS_ 2000
#define NH_ 16
#define NG_ 32
#define NR_ 15

#define NTPAD_ 744          // g_v4 / g_pe planes (prefetch overrun pad)
#define NTQ_   736          // g_Qs planes (scan writes t<736)

// ---------------- scratch (device globals; no allocations allowed) ----------------
__device__ float g_hfc [NS_ * 256];
__device__ float g_hR  [NS_ * 256];
__device__ float g_base1[NS_ * 256];
__device__ float g_base2[NS_ * 256];
__device__ float g_params[8][NS_ * NH_];
__device__ float g_rr  [NS_ * NH_ * 16];          // ga*relu(wR) taps, lag-indexed
__device__ uint2  g_PW  [6144];                   // W frag-packed, tf32 bits
__device__ float  g_c1  [256];                    // fcT1_W1 LAI col
__device__ float4 g_dvec[256];                    // fcT2_W1 {R,T1,T2} cols
__device__ float  g_bias48[48];
__device__ float4 g_v4 [NTPAD_ * NS_ * NH_];      // {Pl1, Pl2, vk, vm}
__device__ float2 g_pe [NTPAD_ * NS_];            // {Ps, E}
__device__ float  g_Qs [NTQ_ * NS_ * NH_];        // per-lane Q1+Q2+Q3

// ---------------- helpers ----------------
__device__ __forceinline__ float tanh_hw(float x) {
    float y;
    asm("tanh.approx.f32 %0, %1;" : "=f"(y) : "f"(x));
    return y;
}
__device__ __forceinline__ unsigned cvt_tf32(float f) {
    unsigned u;
    asm("cvt.rna.tf32.f32 %0, %1;" : "=r"(u) : "f"(f));
    return u;
}
#define MMA_TF32(D, a0, a1, a2, a3, b0, b1)                                   \
    asm("mma.sync.aligned.m16n8k8.row.col.f32.tf32.tf32.f32 "                 \
        "{%0,%1,%2,%3}, {%4,%5,%6,%7}, {%8,%9}, {%0,%1,%2,%3};"               \
        : "+f"((D)[0]), "+f"((D)[1]), "+f"((D)[2]), "+f"((D)[3])              \
        : "r"(a0), "r"(a1), "r"(a2), "r"(a3), "r"(b0), "r"(b1))

// ============================================================================
// Kernel 1a: per-basin hidden activations + time-invariant layer-1 bases
// ============================================================================
__global__ void __launch_bounds__(256) k_hidden(
    const float* __restrict__ xc,
    const float* __restrict__ fc_W1,  const float* __restrict__ fc_b1,
    const float* __restrict__ fcR_W1, const float* __restrict__ fcR_b1,
    const float* __restrict__ fcT1_W1, const float* __restrict__ fcT1_b1,
    const float* __restrict__ fcT2_W1, const float* __restrict__ fcT2_b1)
{
    __shared__ float xcs[8][NG_];
    const int tid = threadIdx.x;
    const int s0  = blockIdx.x * 8;
    xcs[tid >> 5][tid & 31] = xc[s0 * NG_ + tid];
    __syncthreads();

    const int j = tid;
    float acc[8];

    {
        float b = fc_b1[j];
#pragma unroll
        for (int i = 0; i < 8; i++) acc[i] = b;
        const float4* row = (const float4*)(fc_W1 + j * NG_);
#pragma unroll
        for (int q = 0; q < 8; q++) {
            float4 w = row[q];
#pragma unroll
            for (int i = 0; i < 8; i++) {
                acc[i] = fmaf(w.x, xcs[i][4*q+0], acc[i]);
                acc[i] = fmaf(w.y, xcs[i][4*q+1], acc[i]);
                acc[i] = fmaf(w.z, xcs[i][4*q+2], acc[i]);
                acc[i] = fmaf(w.w, xcs[i][4*q+3], acc[i]);
            }
        }
#pragma unroll
        for (int i = 0; i < 8; i++) g_hfc[(s0 + i) * 256 + j] = tanhf(acc[i]);
    }
    {
        float b = fcR_b1[j];
#pragma unroll
        for (int i = 0; i < 8; i++) acc[i] = b;
        const float4* row = (const float4*)(fcR_W1 + j * NG_);
#pragma unroll
        for (int q = 0; q < 8; q++) {
            float4 w = row[q];
#pragma unroll
            for (int i = 0; i < 8; i++) {
                acc[i] = fmaf(w.x, xcs[i][4*q+0], acc[i]);
                acc[i] = fmaf(w.y, xcs[i][4*q+1], acc[i]);
                acc[i] = fmaf(w.z, xcs[i][4*q+2], acc[i]);
                acc[i] = fmaf(w.w, xcs[i][4*q+3], acc[i]);
            }
        }
#pragma unroll
        for (int i = 0; i < 8; i++) g_hR[(s0 + i) * 256 + j] = tanhf(acc[i]);
    }
    {
        float b = fcT1_b1[j];
#pragma unroll
        for (int i = 0; i < 8; i++) acc[i] = b;
        const float* row = fcT1_W1 + j * 33 + 1;
#pragma unroll
        for (int g = 0; g < NG_; g++) {
            float w = row[g];
#pragma unroll
            for (int i = 0; i < 8; i++) acc[i] = fmaf(w, xcs[i][g], acc[i]);
        }
#pragma unroll
        for (int i = 0; i < 8; i++) g_base1[(s0 + i) * 256 + j] = acc[i];
    }
    {
        float b = fcT2_b1[j];
#pragma unroll
        for (int i = 0; i < 8; i++) acc[i] = b;
        const float* row = fcT2_W1 + j * 35 + 3;
#pragma unroll
        for (int g = 0; g < NG_; g++) {
            float w = row[g];
#pragma unroll
            for (int i = 0; i < 8; i++) acc[i] = fmaf(w, xcs[i][g], acc[i]);
        }
#pragma unroll
        for (int i = 0; i < 8; i++) g_base2[(s0 + i) * 256 + j] = acc[i];
    }
}

// ============================================================================
// Kernel 1b: per-basin output layers -> scan params + routing taps
// ============================================================================
__global__ void __launch_bounds__(256) k_outputs(
    const float* __restrict__ fc_W2,  const float* __restrict__ fc_b2,
    const float* __restrict__ fcR_W2, const float* __restrict__ fcR_b2)
{
    __shared__ float hf[8][256];
    __shared__ float hr[8][256];
    __shared__ float w8[8][160];
    __shared__ float r8[8][240];
    __shared__ float ga8[8][NH_];

    const int tid = threadIdx.x;
    const int s0  = blockIdx.x * 8;

    for (int idx = tid; idx < 2048; idx += 256) {
        int b = idx >> 8, j = idx & 255;
        hf[b][j] = g_hfc[(s0 + b) * 256 + j];
        hr[b][j] = g_hR [(s0 + b) * 256 + j];
    }
    __syncthreads();

    if (tid < 160) {
        const int o = tid;
        float acc[8];
        float bb = fc_b2[o];
#pragma unroll
        for (int i = 0; i < 8; i++) acc[i] = bb;
        const float4* row = (const float4*)(fc_W2 + o * 256);
        for (int q = 0; q < 64; q++) {
            float4 w = row[q];
#pragma unroll
            for (int i = 0; i < 8; i++) {
                acc[i] = fmaf(w.x, hf[i][4*q+0], acc[i]);
                acc[i] = fmaf(w.y, hf[i][4*q+1], acc[i]);
                acc[i] = fmaf(w.z, hf[i][4*q+2], acc[i]);
                acc[i] = fmaf(w.w, hf[i][4*q+3], acc[i]);
            }
        }
#pragma unroll
        for (int i = 0; i < 8; i++) w8[i][o] = acc[i];
    }
    if (tid < 240) {
        const int o = tid;
        float acc[8];
        float bb = fcR_b2[o];
#pragma unroll
        for (int i = 0; i < 8; i++) acc[i] = bb;
        const float4* row = (const float4*)(fcR_W2 + o * 256);
        for (int q = 0; q < 64; q++) {
            float4 w = row[q];
#pragma unroll
            for (int i = 0; i < 8; i++) {
                acc[i] = fmaf(w.x, hr[i][4*q+0], acc[i]);
                acc[i] = fmaf(w.y, hr[i][4*q+1], acc[i]);
                acc[i] = fmaf(w.z, hr[i][4*q+2], acc[i]);
                acc[i] = fmaf(w.w, hr[i][4*q+3], acc[i]);
            }
        }
#pragma unroll
        for (int i = 0; i < 8; i++) r8[i][o] = fmaxf(acc[i], 0.f);
    }
    __syncthreads();

    if (tid < 128) {
        const int b = tid >> 4, h = tid & 15;
        const float* wb = w8[b];
        float k1  = 1.f / (1.f + expf(-wb[16  + h]));
        float k2  = 1.f / (1.f + expf(-wb[32  + h]));
        float k23 = 1.f / (1.f + expf(-wb[48  + h]));
        float k3  = (1.f / (1.f + expf(-wb[64 + h]))) * 0.1f;
        float gl  = expf(wb[80 + h]) * 2.f;
        float qb  = fmaxf(wb[112 + h], 0.f);
        float ge1 = fmaxf(wb[128 + h], 0.f);
        float ge2 = fmaxf(wb[144 + h], 0.f);
        float m = wb[96];
        for (int i = 1; i < 16; i++) m = fmaxf(m, wb[96 + i]);
        float sum = 0.f;
        for (int i = 0; i < 16; i++) sum += expf(wb[96 + i] - m);
        float ga = expf(wb[96 + h] - m) / sum;
        ga8[b][h] = ga;

        const int lane = (s0 + b) * NH_ + h;
        g_params[0][lane] = k1;
        g_params[1][lane] = k2;
        g_params[2][lane] = k23;
        g_params[3][lane] = k3;
        g_params[4][lane] = gl;
        g_params[5][lane] = qb;
        g_params[6][lane] = ge1;
        g_params[7][lane] = ge2;
        g_rr[lane * 16 + 15] = 0.f;
    }
    __syncthreads();

    for (int idx = tid; idx < 8 * 240; idx += 256) {
        int b = idx / 240, o = idx % 240;
        int h = o / NR_, jj = o % NR_;
        int lane = (s0 + b) * NH_ + h;
        g_rr[lane * 16 + (14 - jj)] = ga8[b][h] * r8[b][o];
    }
}

// ============================================================================
// Kernel 1c: pack layer-2 weights into mma B-fragment layout (tf32 bits)
// ============================================================================
__global__ void __launch_bounds__(256) k_prep(
    const float* __restrict__ fcT1_W1, const float* __restrict__ fcT1_W2,
    const float* __restrict__ fcT1_b2,
    const float* __restrict__ fcT2_W1, const float* __restrict__ fcT2_W2,
    const float* __restrict__ fcT2_b2)
{
    const int idx = blockIdx.x * 256 + threadIdx.x;   // 0..6143
    {
        const int kk   = idx / 192;
        const int rem  = idx % 192;
        const int nt   = rem / 32;
        const int lane = rem % 32;
        const int j    = kk * 8 + (lane & 3);
        const int oo   = lane >> 2;
        float w0, w1;
        if (nt < 4) {
            int o = nt * 8 + oo;
            w0 = fcT1_W2[o * 256 + j];
            w1 = fcT1_W2[o * 256 + j + 4];
        } else {
            int o = (nt - 4) * 8 + oo;
            w0 = fcT2_W2[o * 256 + j];
            w1 = fcT2_W2[o * 256 + j + 4];
        }
        uint2 u;
        u.x = cvt_tf32(w0);
        u.y = cvt_tf32(w1);
        g_PW[idx] = u;
    }
    if (idx < 256) {
        g_c1[idx] = fcT1_W1[idx * 33];
        float4 dv;
        dv.x = fcT2_W1[idx * 35 + 0];
        dv.y = fcT2_W1[idx * 35 + 1];
        dv.z = fcT2_W1[idx * 35 + 2];
        dv.w = 0.f;
        g_dvec[idx] = dv;
    }
    if (idx < 48) g_bias48[idx] = (idx < 32) ? fcT1_b2[idx] : fcT2_b2[idx - 32];
}

// ============================================================================
// Kernel 2: tensor-core per-(t,s) MLPs -> {Pl1,Pl2,vk,vm} + {Ps,E}
// block = 2 basins x 128 timesteps, 8 warps (4 per basin); register epilogue
// (R11 tf32 version — proven 296us; bf16 variant regressed)
// ============================================================================
// smem word offsets
#define SMO_DVEC  0                       // float4[256]        -> 1024 words
#define SMO_PW    1024                    // uint2[6144]        -> 12288
#define SMO_COEF1 13312                   // float2[2*256]      -> 1024
#define SMO_BASE2 14336                   // float [2*256]      -> 512
#define SMO_XS    14848                   // float4[2*128]      -> 1024 {Ta,Tb,Rv,LAI}
#define SMO_PL    15872                   // float [2*128]      -> 256
#define SMO_BIAS  16128                   // float [48]
#define KM_SMEM_WORDS 16176
#define KM_SMEM_BYTES (KM_SMEM_WORDS * 4)

__global__ void __launch_bounds__(256) k_mlp_tc(const float* __restrict__ x)
{
    extern __shared__ float sm[];
    float4* sdvec  = (float4*)(sm + SMO_DVEC);
    uint2*  sPW    = (uint2*)(sm + SMO_PW);
    float2* scoef1 = (float2*)(sm + SMO_COEF1);
    float*  sbase2 = sm + SMO_BASE2;
    float4* sxs    = (float4*)(sm + SMO_XS);
    float*  sPL    = sm + SMO_PL;
    float*  sbias  = sm + SMO_BIAS;

    const int tid = threadIdx.x;
    const int s0  = blockIdx.x * 2;
    const int t0  = blockIdx.y << 7;

    for (int i = tid; i < 6144; i += 256) sPW[i] = g_PW[i];
    for (int i = tid; i < 256; i += 256) sdvec[i] = g_dvec[i];
    for (int i = tid; i < 512; i += 256) {
        int g = i >> 8, j = i & 255;
        scoef1[i] = make_float2(g_base1[(s0 + g) * 256 + j], g_c1[j]);
        sbase2[i] = g_base2[(s0 + g) * 256 + j];
    }
    if (tid < 48) sbias[tid] = g_bias48[tid];

    // prologue: one thread per (basin, row): forcings + vp/Ps/Pl
    {
        const int g = tid >> 7, r = tid & 127;
        const int t = t0 + r;
        const int s = s0 + g;
        float P = 0.f, E = 0.f, Ta = 0.f, Tb = 0.f, Rv = 0.f, LAI = 0.f;
        if (t < NT_) {
            const float* xr = x + ((size_t)t * NS_ + s) * 6;
            P = __ldg(xr); E = __ldg(xr + 1); Ta = __ldg(xr + 2);
            Tb = __ldg(xr + 3); Rv = __ldg(xr + 4); LAI = __ldg(xr + 5);
        }
        sxs[g * 128 + r] = make_float4(Ta, Tb, Rv, LAI);

        float den = Tb - Ta;
        float ra  = (Ta + Tb) / (den == 0.f ? 1.f : den);
        ra = fminf(fmaxf(ra, -1.f), 1.f);
        if (Ta >= 0.f || Tb <= 0.f) ra = 0.f;
        float vp = 1.f - acosf(ra) * (1.f / 3.1415f);
        if (Ta >= 0.f) vp = 1.f;
        if (Tb <= 0.f) vp = 0.f;
        float Ps = P * (1.f - vp);
        float Pl = P * vp;
        sPL[g * 128 + r] = Pl;
        if (t < NT_) __stcs(g_pe + (size_t)t * NS_ + s, make_float2(Ps, E));
    }
    __syncthreads();

    const int g    = tid >> 7;
    const int wl   = (tid >> 5) & 3;
    const int lane = tid & 31;
    const int rq = lane >> 2, qk = lane & 3;
    const int rbase = wl * 32 + rq;
    const int s = s0 + g;

    float LAI[4], Rv[4], Ta[4], Tb[4];
#pragma unroll
    for (int i = 0; i < 4; i++) {
        float4 xr = sxs[g * 128 + rbase + i * 8];
        Ta[i] = xr.x; Tb[i] = xr.y; Rv[i] = xr.z; LAI[i] = xr.w;
    }

    float dacc[2][6][4];
#pragma unroll
    for (int mt = 0; mt < 2; mt++)
#pragma unroll
        for (int nt = 0; nt < 6; nt++)
#pragma unroll
            for (int r = 0; r < 4; r++) dacc[mt][nt][r] = 0.f;

#pragma unroll 2
    for (int kk = 0; kk < 32; kk++) {
        const int j0 = kk * 8 + qk;
        const uint2* pb = sPW + kk * 192 + lane;

        // ---- G1: h1 = tanh(base1 + LAI*c1), n-tiles 0..3 (vi, vk) ----
        float2 c0  = scoef1[g * 256 + j0];
        float2 c1v = scoef1[g * 256 + j0 + 4];
        unsigned aA[8];
#pragma unroll
        for (int i = 0; i < 4; i++) {
            float hA = tanh_hw(fmaf(LAI[i], c0.y,  c0.x));
            float hB = tanh_hw(fmaf(LAI[i], c1v.y, c1v.x));
            aA[(i >> 1) * 4 + (i & 1)]     = __float_as_uint(hA);   // HW truncates to tf32
            aA[(i >> 1) * 4 + 2 + (i & 1)] = __float_as_uint(hB);
        }
#pragma unroll
        for (int nt = 0; nt < 4; nt++) {
            uint2 b = pb[nt * 32];
            MMA_TF32(dacc[0][nt], aA[0], aA[1], aA[2], aA[3], b.x, b.y);
            MMA_TF32(dacc[1][nt], aA[4], aA[5], aA[6], aA[7], b.x, b.y);
        }

        // ---- G2: h2 = tanh(base2 + R*d0 + T1*d1 + T2*d2), n-tiles 4..5 (vm) ----
        float  b20 = sbase2[g * 256 + j0], b21 = sbase2[g * 256 + j0 + 4];
        float4 dv0 = sdvec[j0],  dv1 = sdvec[j0 + 4];
        unsigned aB[8];
#pragma unroll
        for (int i = 0; i < 4; i++) {
            float p = fmaf(Rv[i], dv0.x, b20);
            p = fmaf(Ta[i], dv0.y, p);
            p = fmaf(Tb[i], dv0.z, p);
            float q = fmaf(Rv[i], dv1.x, b21);
            q = fmaf(Ta[i], dv1.y, q);
            q = fmaf(Tb[i], dv1.z, q);
            aB[(i >> 1) * 4 + (i & 1)]     = __float_as_uint(tanh_hw(p));
            aB[(i >> 1) * 4 + 2 + (i & 1)] = __float_as_uint(tanh_hw(q));
        }
#pragma unroll
        for (int nt = 4; nt < 6; nt++) {
            uint2 b = pb[nt * 32];
            MMA_TF32(dacc[0][nt], aB[0], aB[1], aB[2], aB[3], b.x, b.y);
            MMA_TF32(dacc[1][nt], aB[4], aB[5], aB[6], aB[7], b.x, b.y);
        }
    }

    // register epilogue: thread owns rows {wl*32+mt*16+rq, +8}, h = {hi*8+2qk, +1}
    const float inv6 = 1.f / 6.f;
#pragma unroll
    for (int mt = 0; mt < 2; mt++) {
#pragma unroll
        for (int half = 0; half < 2; half++) {
            const int r = wl * 32 + mt * 16 + rq + half * 8;
            const int t = t0 + r;
            if (t < NT_) {
                const float Pl = sPL[g * 128 + r];
                float4* dst = g_v4 + ((size_t)t * NS_ + s) * NH_;
#pragma unroll
                for (int hi = 0; hi < 2; hi++) {
#pragma unroll
                    for (int c = 0; c < 2; c++) {
                        const int h  = hi * 8 + 2 * qk + c;
                        const int di = half * 2 + c;
                        float vi = __saturatef(fmaf(dacc[mt][hi][di]     + sbias[h],      inv6, 0.5f));
                        float vk = __saturatef(fmaf(dacc[mt][2 + hi][di] + sbias[16 + h], inv6, 0.5f));
                        float vm = __expf(2.f * (dacc[mt][4 + hi][di] + sbias[32 + h]));
                        float Pl2 = Pl * vi;
                        __stcs(dst + h, make_float4(Pl - Pl2, Pl2, vk, vm));
                    }
                }
            }
        }
    }
}

// ============================================================================
// Kernel 3: pure recurrence; 1 lane/thread, 8-deep double-buffered prefetch.
// 92 chunks of 8 t-steps (processes t<736; padding zero-filled and unread).
// ============================================================================
#define PLV_ (NS_ * NH_)

__global__ void __launch_bounds__(128) k_scan3()
{
    const int lane = blockIdx.x * 128 + threadIdx.x;   // 0..31999

    const float k1  = g_params[0][lane];
    const float k2  = g_params[1][lane];
    const float k23 = g_params[2][lane];
    const float k3  = g_params[3][lane];
    const float gl  = g_params[4][lane];
    const float qb  = g_params[5][lane];
    const float ge1 = g_params[6][lane];
    const float ge2 = g_params[7][lane];
    const float c23 = 1.f - k23;

    const float4* pv = g_v4 + lane;
    const float2* pp = g_pe + (lane >> 4);

    float4 bv0[8], bv1[8];
    float2 bp0[8], bp1[8];
#pragma unroll
    for (int u = 0; u < 8; u++) {
        bv0[u] = __ldcs(pv + (size_t)u * PLV_);
        bp0[u] = __ldcs(pp + u * NS_);
    }

    float S0 = 0.f, Sv = 0.f, S2 = 0.f, S3 = 0.f;

#define STEP(V, PE, T)                                                         \
    {                                                                          \
        float H0  = S0 + (PE).x;                                               \
        float qSm = fminf(H0, (V).w);                                          \
        float Hv  = fmaxf(Sv + (V).x - (PE).y * ge1, 0.f);                     \
        float qv  = Sv * (V).z;                                                \
        float H2  = fmaxf(S2 + qSm + qv - (PE).y * ge2 + (V).y, 0.f);          \
        float x1  = H2 - gl;                                                   \
        float Q1  = (x1 > 0.f) ? __powf(x1, k1) : 0.f;                         \
        float q2v = fminf(H2, gl) * k2;                                        \
        float H3  = fmaf(q2v, k23, S3);                                        \
        float Q3  = fmaf(H3, k3, qb);                                          \
        S0 = H0 - qSm;                                                         \
        Sv = Hv - qv;                                                          \
        S2 = H2 - Q1 - q2v;                                                    \
        S3 = H3 - Q3;                                                          \
        __stcs(g_Qs + (size_t)(T) * PLV_ + lane, Q1 + q2v * c23 + Q3);         \
    }

#pragma unroll 1
    for (int c = 0; c < 92; c += 2) {
#pragma unroll
        for (int u = 0; u < 8; u++) {
            bv1[u] = __ldcs(pv + (size_t)((c + 1) * 8 + u) * PLV_);
            bp1[u] = __ldcs(pp + ((c + 1) * 8 + u) * NS_);
        }
#pragma unroll
        for (int u = 0; u < 8; u++) STEP(bv0[u], bp0[u], c * 8 + u)
#pragma unroll
        for (int u = 0; u < 8; u++) {
            bv0[u] = __ldcs(pv + (size_t)((c + 2) * 8 + u) * PLV_);
            bp0[u] = __ldcs(pp + ((c + 2) * 8 + u) * NS_);
        }
#pragma unroll
        for (int u = 0; u < 8; u++) STEP(bv1[u], bp1[u], (c + 1) * 8 + u)
    }
#undef STEP
}

// ============================================================================
// Kernel 4: causal 15-tap routing conv + h-reduction (parallel).
// ============================================================================
__global__ void __launch_bounds__(256) k_route(float* __restrict__ out)
{
    __shared__ float sQ[270 * 20];
    __shared__ float srr[15 * 16];

    const int tid = threadIdx.x;
    const int s   = blockIdx.x;
    const int t0  = blockIdx.y << 8;

    for (int i = tid; i < 270 * 16; i += 256) {
        int row = i >> 4, h = i & 15;
        int tg = t0 + row - 14;
        sQ[row * 20 + h] = (tg >= 0 && tg < NT_)
                         ? g_Qs[(size_t)tg * (NS_ * NH_) + s * NH_ + h] : 0.f;
    }
    if (tid < 240) {
        int d = tid >> 4, h = tid & 15;
        srr[d * 16 + h] = g_rr[(s * NH_ + h) * 16 + d];
    }
    __syncthreads();

    const int t = t0 + tid;
    if (t < NT_) {
        float4 acc = make_float4(0.f, 0.f, 0.f, 0.f);
#pragma unroll
        for (int d = 0; d < 15; d++) {
            const float4* qr  = (const float4*)(sQ + (tid + 14 - d) * 20);
            const float4* rr4 = (const float4*)(srr + d * 16);
#pragma unroll
            for (int hq = 0; hq < 4; hq++) {
                float4 q = qr[hq];
                float4 r = rr4[hq];
                acc.x = fmaf(q.x, r.x, acc.x);
                acc.y = fmaf(q.y, r.y, acc.y);
                acc.z = fmaf(q.z, r.z, acc.z);
                acc.w = fmaf(q.w, r.w, acc.w);
            }
        }
        out[(size_t)t * NS_ + s] = (acc.x + acc.y) + (acc.z + acc.w);
    }
}

// ============================================================================
// launch
// ============================================================================
extern "C" void kernel_launch(void* const* d_in, const int* in_sizes, int n_in,
                              void* d_out, int out_size)
{
    const float* x       = (const float*)d_in[0];
    const float* xc      = (const float*)d_in[1];
    const float* fc_W1   = (const float*)d_in[2];
    const float* fc_b1   = (const float*)d_in[3];
    const float* fc_W2   = (const float*)d_in[4];
    const float* fc_b2   = (const float*)d_in[5];
    const float* fcR_W1  = (const float*)d_in[6];
    const float* fcR_b1  = (const float*)d_in[7];
    const float* fcR_W2  = (const float*)d_in[8];
    const float* fcR_b2  = (const float*)d_in[9];
    const float* fcT1_W1 = (const float*)d_in[10];
    const float* fcT1_b1 = (const float*)d_in[11];
    const float* fcT1_W2 = (const float*)d_in[12];
    const float* fcT1_b2 = (const float*)d_in[13];
    const float* fcT2_W1 = (const float*)d_in[14];
    const float* fcT2_b1 = (const float*)d_in[15];
    const float* fcT2_W2 = (const float*)d_in[16];
    const float* fcT2_b2 = (const float*)d_in[17];
    float* out = (float*)d_out;

    cudaFuncSetAttribute(k_mlp_tc, cudaFuncAttributeMaxDynamicSharedMemorySize, KM_SMEM_BYTES);

    k_hidden<<<NS_ / 8, 256>>>(xc, fc_W1, fc_b1, fcR_W1, fcR_b1,
                               fcT1_W1, fcT1_b1, fcT2_W1, fcT2_b1);
    k_outputs<<<NS_ / 8, 256>>>(fc_W2, fc_b2, fcR_W2, fcR_b2);
    k_prep<<<24, 256>>>(fcT1_W1, fcT1_W2, fcT1_b2, fcT2_W1, fcT2_W2, fcT2_b2);
    k_mlp_tc<<<dim3(NS_ / 2, 6), 256, KM_SMEM_BYTES>>>(x);
    k_scan3<<<(NS_ * NH_) / 128, 128>>>();
    k_route<<<dim3(NS_, 3), 256>>>(out);
}